// round 4
// baseline (speedup 1.0000x reference)
#include <cuda_runtime.h>
#include <math.h>

#define N 8192
#define D 512
#define TOPK 20
#define COLSPLIT 4
#define COLS_PER_BLOCK (N / COLSPLIT)   // 2048
#define TILE_M 32
#define TILE_N 128
#define TILE_K 32

#define NEG_INF (__int_as_float(0xff800000))

// Scratch (device globals; no runtime allocation allowed)
__device__ float g_Q[N * D];                       // 16 MB
__device__ float g_K[N * D];                       // 16 MB
__device__ float g_topv[N * COLSPLIT * TOPK];      // partial top-20 values
__device__ int   g_topi[N * COLSPLIT * TOPK];      // partial top-20 indices

// ---------------------------------------------------------------------------
// Kernel A: Q = h @ Wq^T, K = h @ Wk^T   (both operands row-major, inner dim D)
// grid (D/128, N/32, 2), 256 threads. Tile 32x128, k-chunk 32, 4x4 micro.
// ---------------------------------------------------------------------------
__global__ void qk_gemm(const float* __restrict__ h,
                        const float* __restrict__ Wq,
                        const float* __restrict__ Wk) {
    const float* __restrict__ W = blockIdx.z ? Wk : Wq;
    float* __restrict__ out = blockIdx.z ? g_K : g_Q;
    const int row0 = blockIdx.y * TILE_M;
    const int col0 = blockIdx.x * TILE_N;

    __shared__ float As[TILE_K][TILE_M + 4];    // [k][i], 16B-aligned rows
    __shared__ float Bs[TILE_K][TILE_N + 4];    // [k][j]

    const int tid = threadIdx.x;
    const int tx = tid & 31;     // 0..31 -> 4 cols each
    const int ty = tid >> 5;     // 0..7  -> 4 rows each
    const int lr = tid >> 3;     // 0..31 (loader row)
    const int lk = (tid & 7) << 2; // 0,4,...,28 (loader k group)

    float acc[4][4] = {};

    for (int k0 = 0; k0 < D; k0 += TILE_K) {
        // A tile: 32 rows x 32 k  (1 float4 per thread)
        {
            float4 a = *(const float4*)(h + (size_t)(row0 + lr) * D + k0 + lk);
            As[lk + 0][lr] = a.x; As[lk + 1][lr] = a.y;
            As[lk + 2][lr] = a.z; As[lk + 3][lr] = a.w;
        }
        // B tile: 128 rows x 32 k  (4 float4 per thread)
        #pragma unroll
        for (int m = 0; m < 4; m++) {
            int r = lr + m * 32;
            float4 b = *(const float4*)(W + (size_t)(col0 + r) * D + k0 + lk);
            Bs[lk + 0][r] = b.x; Bs[lk + 1][r] = b.y;
            Bs[lk + 2][r] = b.z; Bs[lk + 3][r] = b.w;
        }
        __syncthreads();

        #pragma unroll 8
        for (int kk = 0; kk < TILE_K; kk++) {
            float4 a4 = *(const float4*)(&As[kk][ty * 4]);
            float4 b4 = *(const float4*)(&Bs[kk][tx * 4]);
            float av[4] = {a4.x, a4.y, a4.z, a4.w};
            float bv[4] = {b4.x, b4.y, b4.z, b4.w};
            #pragma unroll
            for (int r = 0; r < 4; r++)
                #pragma unroll
                for (int c = 0; c < 4; c++)
                    acc[r][c] = fmaf(av[r], bv[c], acc[r][c]);
        }
        __syncthreads();
    }

    #pragma unroll
    for (int r = 0; r < 4; r++) {
        float4 v = make_float4(acc[r][0], acc[r][1], acc[r][2], acc[r][3]);
        *(float4*)(out + (size_t)(row0 + ty * 4 + r) * D + col0 + tx * 4) = v;
    }
}

// ---------------------------------------------------------------------------
// Kernel B: fused logits (Q Kt / sqrt(D) + ps*prior, diag=-inf) + streaming
// per-row top-20 over this block's 2048-column slab. Logits never hit DRAM.
// grid (COLSPLIT, N/32), 256 threads.
// ---------------------------------------------------------------------------
__global__ void logits_topk(const float* __restrict__ prior,
                            const float* __restrict__ pscale_p) {
    const int row0  = blockIdx.y * TILE_M;
    const int cbase = blockIdx.x * COLS_PER_BLOCK;
    const float ps = *pscale_p;
    const float scale = 0.04419417382415922f;   // 1/sqrt(512)

    __shared__ float As[TILE_K][TILE_M + 4];
    __shared__ float Bs[TILE_K][TILE_N + 4];
    __shared__ float Ssh[TILE_M][TILE_N + 4];
    __shared__ float s_topv[TILE_M][TOPK];
    __shared__ int   s_topi[TILE_M][TOPK];

    const int tid = threadIdx.x;
    const int tx = tid & 31;
    const int ty = tid >> 5;
    const int lr = tid >> 3;
    const int lk = (tid & 7) << 2;

    if (tid < TILE_M) {
        #pragma unroll
        for (int s = 0; s < TOPK; s++) {
            s_topv[tid][s] = NEG_INF;
            s_topi[tid][s] = 0;
        }
    }
    float curmin = NEG_INF;
    int minpos = 0;
    __syncthreads();

    for (int t = 0; t < COLS_PER_BLOCK / TILE_N; t++) {
        const int col0 = cbase + t * TILE_N;
        float acc[4][4] = {};

        for (int k0 = 0; k0 < D; k0 += TILE_K) {
            {
                float4 a = *(const float4*)(g_Q + (size_t)(row0 + lr) * D + k0 + lk);
                As[lk + 0][lr] = a.x; As[lk + 1][lr] = a.y;
                As[lk + 2][lr] = a.z; As[lk + 3][lr] = a.w;
            }
            #pragma unroll
            for (int m = 0; m < 4; m++) {
                int r = lr + m * 32;
                float4 b = *(const float4*)(g_K + (size_t)(col0 + r) * D + k0 + lk);
                Bs[lk + 0][r] = b.x; Bs[lk + 1][r] = b.y;
                Bs[lk + 2][r] = b.z; Bs[lk + 3][r] = b.w;
            }
            __syncthreads();

            #pragma unroll 8
            for (int kk = 0; kk < TILE_K; kk++) {
                float4 a4 = *(const float4*)(&As[kk][ty * 4]);
                float4 b4 = *(const float4*)(&Bs[kk][tx * 4]);
                float av[4] = {a4.x, a4.y, a4.z, a4.w};
                float bv[4] = {b4.x, b4.y, b4.z, b4.w};
                #pragma unroll
                for (int r = 0; r < 4; r++)
                    #pragma unroll
                    for (int c = 0; c < 4; c++)
                        acc[r][c] = fmaf(av[r], bv[c], acc[r][c]);
            }
            __syncthreads();
        }

        // Epilogue: scale + prior + diagonal mask -> Ssh
        #pragma unroll
        for (int r = 0; r < 4; r++) {
            const int gi = row0 + ty * 4 + r;
            const int gj = col0 + tx * 4;
            float4 p4 = *(const float4*)(prior + (size_t)gi * N + gj);
            float v[4];
            v[0] = fmaf(ps, p4.x, acc[r][0] * scale);
            v[1] = fmaf(ps, p4.y, acc[r][1] * scale);
            v[2] = fmaf(ps, p4.z, acc[r][2] * scale);
            v[3] = fmaf(ps, p4.w, acc[r][3] * scale);
            #pragma unroll
            for (int c = 0; c < 4; c++)
                Ssh[ty * 4 + r][tx * 4 + c] = (gi == gj + c) ? NEG_INF : v[c];
        }
        __syncthreads();

        // Streaming top-20 update: one thread per row (warp 0).
        // Strict '>' keeps the earliest (lowest) index on exact ties,
        // matching jax.lax.top_k tie-breaking.
        if (tid < TILE_M) {
            for (int j = 0; j < TILE_N; j++) {
                float v = Ssh[tid][j];
                if (v > curmin) {
                    s_topv[tid][minpos] = v;
                    s_topi[tid][minpos] = col0 + j;
                    float m = s_topv[tid][0];
                    int mp = 0;
                    #pragma unroll
                    for (int s = 1; s < TOPK; s++) {
                        float tv = s_topv[tid][s];
                        if (tv < m) { m = tv; mp = s; }
                    }
                    curmin = m;
                    minpos = mp;
                }
            }
        }
        __syncthreads();
    }

    if (tid < TILE_M) {
        int row = row0 + tid;
        size_t base = ((size_t)row * COLSPLIT + blockIdx.x) * TOPK;
        #pragma unroll
        for (int s = 0; s < TOPK; s++) {
            g_topv[base + s] = s_topv[tid][s];
            g_topi[base + s] = s_topi[tid][s];
        }
    }
}

// ---------------------------------------------------------------------------
// Zero the 256 MB output (d_out is poisoned by the harness).
// ---------------------------------------------------------------------------
__global__ void zero_out(float4* __restrict__ out) {
    size_t i = (size_t)blockIdx.x * blockDim.x + threadIdx.x;
    const size_t stride = (size_t)gridDim.x * blockDim.x;
    const size_t n = (size_t)N * N / 4;
    const float4 z = make_float4(0.f, 0.f, 0.f, 0.f);
    for (; i < n; i += stride) out[i] = z;
}

// ---------------------------------------------------------------------------
// Kernel D: merge 4 partial lists (80 candidates) -> global top-20, softmax,
// scatter into the zeroed output. One thread per row.
// ---------------------------------------------------------------------------
__global__ void softmax_scatter(float* __restrict__ out) {
    int row = blockIdx.x * blockDim.x + threadIdx.x;
    if (row >= N) return;

    float tv[TOPK];
    int ti[TOPK];
    #pragma unroll
    for (int s = 0; s < TOPK; s++) { tv[s] = NEG_INF; ti[s] = 0; }
    float curmin = NEG_INF;
    int minpos = 0;

    size_t base = (size_t)row * (COLSPLIT * TOPK);
    for (int c = 0; c < COLSPLIT * TOPK; c++) {
        float v = g_topv[base + c];
        if (v > curmin) {
            tv[minpos] = v;
            ti[minpos] = g_topi[base + c];
            float m = tv[0];
            int mp = 0;
            #pragma unroll
            for (int s = 1; s < TOPK; s++)
                if (tv[s] < m) { m = tv[s]; mp = s; }
            curmin = m;
            minpos = mp;
        }
    }

    float mx = tv[0];
    #pragma unroll
    for (int s = 1; s < TOPK; s++) mx = fmaxf(mx, tv[s]);

    float e[TOPK];
    float sum = 0.f;
    #pragma unroll
    for (int s = 0; s < TOPK; s++) {
        e[s] = expf(tv[s] - mx);
        sum += e[s];
    }
    float inv = 1.0f / sum;

    size_t rbase = (size_t)row * N;
    #pragma unroll
    for (int s = 0; s < TOPK; s++)
        out[rbase + ti[s]] = e[s] * inv;
}

// ---------------------------------------------------------------------------
extern "C" void kernel_launch(void* const* d_in, const int* in_sizes, int n_in,
                              void* d_out, int out_size) {
    const float* h      = (const float*)d_in[0];
    const float* prior  = (const float*)d_in[1];
    const float* Wq     = (const float*)d_in[2];
    const float* Wk     = (const float*)d_in[3];
    const float* pscale = (const float*)d_in[4];
    float* out = (float*)d_out;

    // Zero output early (independent of everything but the scatter).
    zero_out<<<8192, 256>>>((float4*)out);

    // Q/K projections: grid (512/128, 8192/32, 2)
    qk_gemm<<<dim3(D / TILE_N, N / TILE_M, 2), 256>>>(h, Wq, Wk);

    // Fused logits + streaming top-20: grid (4, 256) = 1024 blocks
    logits_topk<<<dim3(COLSPLIT, N / TILE_M), 256>>>(prior, pscale);

    // Merge + softmax + scatter
    softmax_scatter<<<N / 256, 256>>>(out);
}

// round 5
// speedup vs baseline: 1.0223x; 1.0223x over previous
#include <cuda_runtime.h>
#include <math.h>

#define N 8192
#define D 512
#define TOPK 20
#define COLSPLIT 8
#define COLS_PER_BLOCK (N / COLSPLIT)          // 1024
#define TM 64
#define TN 256
#define TK 32
#define TILES_PER_BLOCK (COLS_PER_BLOCK / TN)  // 4

#define AS2_STRIDE (TM + 2)                    // 66 (u64 units)
#define BS_STRIDE  (TN + 4)                    // 260 floats (1040B, /16 ok, /4 ok)
#define SSH_STRIDE 129
#define TOP_STRIDE 21

#define AS2_BYTES (TK * AS2_STRIDE * 8)        // 16896
#define BS_BYTES  (TK * BS_STRIDE * 4)         // 33280
#define SSH_BYTES (TM * SSH_STRIDE * 4)        // 33024
#define TOPV_BYTES (TM * TOP_STRIDE * 4)       // 5376
#define TOPI_BYTES (TM * TOP_STRIDE * 4)       // 5376

#define NEG_INF (__int_as_float(0xff800000))

typedef unsigned long long u64;

__device__ float g_Q[N * D];
__device__ float g_K[N * D];
__device__ float g_topv[N * COLSPLIT * TOPK];
__device__ int   g_topi[N * COLSPLIT * TOPK];

__device__ __forceinline__ u64 dup2(float x) {
    unsigned u = __float_as_uint(x);
    u64 r;
    asm("mov.b64 %0, {%1, %1};" : "=l"(r) : "r"(u));
    return r;
}
__device__ __forceinline__ void ffma2(u64& acc, u64 a, u64 b) {
    asm("fma.rn.f32x2 %0, %1, %2, %0;" : "+l"(acc) : "l"(a), "l"(b));
}
__device__ __forceinline__ float2 unp2(u64 v) {
    float2 f;
    asm("mov.b64 {%0, %1}, %2;" : "=f"(f.x), "=f"(f.y) : "l"(v));
    return f;
}

// ---------------------------------------------------------------------------
// Shared 64x256 fp32 tile mainloop using packed f32x2 FFMA.
// acc[r][p]: rows ty*8+r; pairs p0,p1 -> cols tx*4..+3 ; p2,p3 -> 128+tx*4..+3
// As2 holds A values pre-duplicated as (x,x) b64 so broadcast operands need no
// pack MOVs; B pairs are natural adjacent floats read as ulonglong2.
// ---------------------------------------------------------------------------
__device__ __forceinline__ void mm_tile(const float* __restrict__ Ag,
                                        const float* __restrict__ Bg,
                                        u64* As2, float* Bs, u64 acc[8][4]) {
    const int tid = threadIdx.x;
    const int tx = tid & 31, ty = tid >> 5;
    const int arow = tid >> 2;           // 0..63
    const int akg  = (tid & 3) << 3;     // 0,8,16,24

    #pragma unroll
    for (int r = 0; r < 8; r++)
        #pragma unroll
        for (int p = 0; p < 4; p++) acc[r][p] = 0ull;

    for (int k0 = 0; k0 < D; k0 += TK) {
        // global loads (issued before barrier -> overlap with previous compute)
        float4 a0 = *(const float4*)(Ag + (size_t)arow * D + k0 + akg);
        float4 a1 = *(const float4*)(Ag + (size_t)arow * D + k0 + akg + 4);
        float4 b[8];
        #pragma unroll
        for (int i = 0; i < 8; i++)
            b[i] = *(const float4*)(Bg + (size_t)tid * D + k0 + i * 4);

        __syncthreads();   // previous kk-compute done reading smem

        As2[(akg + 0) * AS2_STRIDE + arow] = dup2(a0.x);
        As2[(akg + 1) * AS2_STRIDE + arow] = dup2(a0.y);
        As2[(akg + 2) * AS2_STRIDE + arow] = dup2(a0.z);
        As2[(akg + 3) * AS2_STRIDE + arow] = dup2(a0.w);
        As2[(akg + 4) * AS2_STRIDE + arow] = dup2(a1.x);
        As2[(akg + 5) * AS2_STRIDE + arow] = dup2(a1.y);
        As2[(akg + 6) * AS2_STRIDE + arow] = dup2(a1.z);
        As2[(akg + 7) * AS2_STRIDE + arow] = dup2(a1.w);
        #pragma unroll
        for (int i = 0; i < 8; i++) {
            Bs[(i * 4 + 0) * BS_STRIDE + tid] = b[i].x;
            Bs[(i * 4 + 1) * BS_STRIDE + tid] = b[i].y;
            Bs[(i * 4 + 2) * BS_STRIDE + tid] = b[i].z;
            Bs[(i * 4 + 3) * BS_STRIDE + tid] = b[i].w;
        }
        __syncthreads();

        #pragma unroll 8
        for (int kk = 0; kk < TK; kk++) {
            const u64* ap = As2 + kk * AS2_STRIDE + ty * 8;
            ulonglong2 aa0 = *(const ulonglong2*)(ap + 0);
            ulonglong2 aa1 = *(const ulonglong2*)(ap + 2);
            ulonglong2 aa2 = *(const ulonglong2*)(ap + 4);
            ulonglong2 aa3 = *(const ulonglong2*)(ap + 6);
            const float* bp = Bs + kk * BS_STRIDE;
            ulonglong2 bb0 = *(const ulonglong2*)(bp + tx * 4);
            ulonglong2 bb1 = *(const ulonglong2*)(bp + 128 + tx * 4);
            u64 av[8] = {aa0.x, aa0.y, aa1.x, aa1.y, aa2.x, aa2.y, aa3.x, aa3.y};
            u64 bv[4] = {bb0.x, bb0.y, bb1.x, bb1.y};
            #pragma unroll
            for (int r = 0; r < 8; r++)
                #pragma unroll
                for (int p = 0; p < 4; p++)
                    ffma2(acc[r][p], av[r], bv[p]);
        }
    }
}

// ---------------------------------------------------------------------------
// Kernel A: Q = h @ Wq^T, K = h @ Wk^T. grid (D/TN, N/TM, 2), 256 threads.
// ---------------------------------------------------------------------------
__global__ void __launch_bounds__(256, 2)
qk_gemm(const float* __restrict__ h,
        const float* __restrict__ Wq,
        const float* __restrict__ Wk) {
    extern __shared__ char sm[];
    u64* As2 = (u64*)sm;
    float* Bs = (float*)(sm + AS2_BYTES);

    const float* __restrict__ W = blockIdx.z ? Wk : Wq;
    float* __restrict__ out = blockIdx.z ? g_K : g_Q;
    const int row0 = blockIdx.y * TM;
    const int col0 = blockIdx.x * TN;

    u64 acc[8][4];
    mm_tile(h + (size_t)row0 * D, W + (size_t)col0 * D, As2, Bs, acc);

    const int tx = threadIdx.x & 31, ty = threadIdx.x >> 5;
    #pragma unroll
    for (int r = 0; r < 8; r++) {
        int row = row0 + ty * 8 + r;
        float2 v0 = unp2(acc[r][0]), v1 = unp2(acc[r][1]);
        *(float4*)(out + (size_t)row * D + col0 + tx * 4) =
            make_float4(v0.x, v0.y, v1.x, v1.y);
        float2 v2 = unp2(acc[r][2]), v3 = unp2(acc[r][3]);
        *(float4*)(out + (size_t)row * D + col0 + 128 + tx * 4) =
            make_float4(v2.x, v2.y, v3.x, v3.y);
    }
}

// ---------------------------------------------------------------------------
// Kernel B: fused logits + streaming per-row top-20 over a 1024-col slab.
// grid (COLSPLIT, N/TM) = (8,128), 256 threads.
// ---------------------------------------------------------------------------
__global__ void __launch_bounds__(256, 2)
logits_topk(const float* __restrict__ prior,
            const float* __restrict__ pscale_p) {
    extern __shared__ char sm[];
    u64*   As2    = (u64*)sm;
    float* Bs     = (float*)(sm + AS2_BYTES);
    float* Ssh    = (float*)(sm + AS2_BYTES + BS_BYTES);
    float* s_topv = (float*)(sm + AS2_BYTES + BS_BYTES + SSH_BYTES);
    int*   s_topi = (int*)  (sm + AS2_BYTES + BS_BYTES + SSH_BYTES + TOPV_BYTES);

    const int tid = threadIdx.x;
    const int tx = tid & 31, ty = tid >> 5;
    const int row0  = blockIdx.y * TM;
    const int cbase = blockIdx.x * COLS_PER_BLOCK;
    const float ps = *pscale_p;
    const float scale = 0.04419417382415922f;   // 1/sqrt(512)

    if (tid < TM) {
        #pragma unroll
        for (int s = 0; s < TOPK; s++) {
            s_topv[tid * TOP_STRIDE + s] = NEG_INF;
            s_topi[tid * TOP_STRIDE + s] = 0;
        }
    }
    float curmin = NEG_INF;
    int minpos = 0;

    for (int t = 0; t < TILES_PER_BLOCK; t++) {
        const int colbase = cbase + t * TN;
        u64 acc[8][4];
        mm_tile(g_Q + (size_t)row0 * D, g_K + (size_t)colbase * D, As2, Bs, acc);

        #pragma unroll
        for (int half = 0; half < 2; half++) {
            // epilogue: scale + prior + diag-mask -> Ssh (128-col chunk)
            #pragma unroll
            for (int r = 0; r < 8; r++) {
                const int lrow = ty * 8 + r;
                const int gi = row0 + lrow;
                const int gj = colbase + half * 128 + tx * 4;
                float4 p4 = *(const float4*)(prior + (size_t)gi * N + gj);
                float2 v0 = unp2(acc[r][half * 2 + 0]);
                float2 v1 = unp2(acc[r][half * 2 + 1]);
                float vv[4] = {v0.x, v0.y, v1.x, v1.y};
                float pp[4] = {p4.x, p4.y, p4.z, p4.w};
                #pragma unroll
                for (int c = 0; c < 4; c++) {
                    float val = fmaf(ps, pp[c], vv[c] * scale);
                    Ssh[lrow * SSH_STRIDE + tx * 4 + c] =
                        (gi == gj + c) ? NEG_INF : val;
                }
            }
            __syncthreads();

            // streaming top-20: one thread per row; strict '>' keeps the
            // earliest (lowest) col index on ties (matches jax.lax.top_k).
            if (tid < TM) {
                const int c0 = colbase + half * 128;
                const float* srow = Ssh + tid * SSH_STRIDE;
                for (int j = 0; j < 128; j++) {
                    float v = srow[j];
                    if (v > curmin) {
                        s_topv[tid * TOP_STRIDE + minpos] = v;
                        s_topi[tid * TOP_STRIDE + minpos] = c0 + j;
                        float m = s_topv[tid * TOP_STRIDE + 0];
                        int mp = 0;
                        #pragma unroll
                        for (int s = 1; s < TOPK; s++) {
                            float tv = s_topv[tid * TOP_STRIDE + s];
                            if (tv < m) { m = tv; mp = s; }
                        }
                        curmin = m;
                        minpos = mp;
                    }
                }
            }
            __syncthreads();
        }
    }

    if (tid < TM) {
        int row = row0 + tid;
        size_t base = ((size_t)row * COLSPLIT + blockIdx.x) * TOPK;
        #pragma unroll
        for (int s = 0; s < TOPK; s++) {
            g_topv[base + s] = s_topv[tid * TOP_STRIDE + s];
            g_topi[base + s] = s_topi[tid * TOP_STRIDE + s];
        }
    }
}

// ---------------------------------------------------------------------------
// Zero the 256 MB output (poisoned by the harness).
// ---------------------------------------------------------------------------
__global__ void zero_out(float4* __restrict__ out) {
    size_t i = (size_t)blockIdx.x * blockDim.x + threadIdx.x;
    const size_t stride = (size_t)gridDim.x * blockDim.x;
    const size_t n = (size_t)N * N / 4;
    const float4 z = make_float4(0.f, 0.f, 0.f, 0.f);
    for (; i < n; i += stride) out[i] = z;
}

// ---------------------------------------------------------------------------
// Merge 8 partial lists (160 candidates) -> top-20, softmax, scatter.
// ---------------------------------------------------------------------------
__global__ void softmax_scatter(float* __restrict__ out) {
    int row = blockIdx.x * blockDim.x + threadIdx.x;
    if (row >= N) return;

    float tv[TOPK];
    int ti[TOPK];
    #pragma unroll
    for (int s = 0; s < TOPK; s++) { tv[s] = NEG_INF; ti[s] = 0; }
    float curmin = NEG_INF;
    int minpos = 0;

    size_t base = (size_t)row * (COLSPLIT * TOPK);
    for (int c = 0; c < COLSPLIT * TOPK; c++) {
        float v = g_topv[base + c];
        if (v > curmin) {
            tv[minpos] = v;
            ti[minpos] = g_topi[base + c];
            float m = tv[0];
            int mp = 0;
            #pragma unroll
            for (int s = 1; s < TOPK; s++)
                if (tv[s] < m) { m = tv[s]; mp = s; }
            curmin = m;
            minpos = mp;
        }
    }

    float mx = tv[0];
    #pragma unroll
    for (int s = 1; s < TOPK; s++) mx = fmaxf(mx, tv[s]);

    float e[TOPK];
    float sum = 0.f;
    #pragma unroll
    for (int s = 0; s < TOPK; s++) {
        e[s] = expf(tv[s] - mx);
        sum += e[s];
    }
    float inv = 1.0f / sum;

    size_t rbase = (size_t)row * N;
    #pragma unroll
    for (int s = 0; s < TOPK; s++)
        out[rbase + ti[s]] = e[s] * inv;
}

// ---------------------------------------------------------------------------
extern "C" void kernel_launch(void* const* d_in, const int* in_sizes, int n_in,
                              void* d_out, int out_size) {
    const float* h      = (const float*)d_in[0];
    const float* prior  = (const float*)d_in[1];
    const float* Wq     = (const float*)d_in[2];
    const float* Wk     = (const float*)d_in[3];
    const float* pscale = (const float*)d_in[4];
    float* out = (float*)d_out;

    const int qk_smem = AS2_BYTES + BS_BYTES;                         // ~49 KB
    const int lt_smem = AS2_BYTES + BS_BYTES + SSH_BYTES
                      + TOPV_BYTES + TOPI_BYTES;                      // ~92 KB
    cudaFuncSetAttribute(qk_gemm, cudaFuncAttributeMaxDynamicSharedMemorySize,
                         qk_smem);
    cudaFuncSetAttribute(logits_topk, cudaFuncAttributeMaxDynamicSharedMemorySize,
                         lt_smem);

    zero_out<<<8192, 256>>>((float4*)out);

    qk_gemm<<<dim3(D / TN, N / TM, 2), 256, qk_smem>>>(h, Wq, Wk);

    logits_topk<<<dim3(COLSPLIT, N / TM), 256, lt_smem>>>(prior, pscale);

    softmax_scatter<<<N / 256, 256>>>(out);
}

// round 13
// speedup vs baseline: 1.8096x; 1.7701x over previous
#include <cuda_runtime.h>
#include <cuda_bf16.h>
#include <math.h>
#include <stdint.h>

#define N 8192
#define D 512
#define TOPK 20
#define SCALE 0.04419417382415922f   // 1/sqrt(512)
#define NEG_INF (__int_as_float(0xff800000))

typedef unsigned long long u64;

// ===== qk_gemm (fp32, FFMA2) config =====
#define TM 64
#define TN 256
#define TK 32
#define AS2_STRIDE (TM + 2)
#define BS_STRIDE  (TN + 4)
#define AS2_BYTES (TK * AS2_STRIDE * 8)
#define BS_BYTES  (TK * BS_STRIDE * 4)

// ===== filter config =====
#define RPC 128                      // rows per CTA
#define CSPLIT 4
#define SLAB (N / CSPLIT)            // 2048
#define FTN 128                      // col tile
#define FTILES (SLAB / FTN)          // 16
#define KC 64                        // K chunk (bf16) = 128B/row
#define CHUNKS (D / KC)              // 8
#define CAND 28
#define CAND_STRIDE 29
#define C_RES 32

// filter smem layout (bytes)
#define SM_A   0
#define SM_B   16384
#define SM_SSH 32768
#define SSH_STRIDE 132               // floats
#define SM_CV  (SM_SSH + RPC * SSH_STRIDE * 4)    // 100352
#define SM_CI  (SM_CV + RPC * CAND_STRIDE * 4)    // 115200
#define SM_TOTAL (SM_CI + RPC * CAND_STRIDE * 4)  // 130048

#define SMEM_SWIZZLE_128B(o) ((o) ^ (((o) >> 3) & 0x70))

// ===== device scratch =====
__device__ float g_Q[N * D];
__device__ float g_K[N * D];
__device__ float4 g_Qb4[N * D / 8];   // bf16 mirror of Q
__device__ float4 g_Kb4[N * D / 8];   // bf16 mirror of K
__device__ float g_cand_v[N * CSPLIT * CAND];
__device__ int   g_cand_i[N * CSPLIT * CAND];

// ===== PTX helpers (all sm_80-era; safe at target sm_103) =====
__device__ __forceinline__ uint32_t smem_u32(const void* p) {
    uint32_t a;
    asm("{ .reg .u64 t; cvta.to.shared.u64 t, %1; cvt.u32.u64 %0, t; }"
        : "=r"(a) : "l"(p));
    return a;
}
__device__ __forceinline__ void ldm4(uint32_t* r, uint32_t addr) {
    asm volatile("ldmatrix.sync.aligned.m8n8.x4.shared.b16 {%0,%1,%2,%3}, [%4];"
        : "=r"(r[0]), "=r"(r[1]), "=r"(r[2]), "=r"(r[3]) : "r"(addr));
}
__device__ __forceinline__ void mma16816(float* c, const uint32_t* a,
                                         uint32_t b0, uint32_t b1) {
    asm volatile(
        "mma.sync.aligned.m16n8k16.row.col.f32.bf16.bf16.f32 "
        "{%0,%1,%2,%3}, {%4,%5,%6,%7}, {%8,%9}, {%0,%1,%2,%3};"
        : "+f"(c[0]), "+f"(c[1]), "+f"(c[2]), "+f"(c[3])
        : "r"(a[0]), "r"(a[1]), "r"(a[2]), "r"(a[3]), "r"(b0), "r"(b1));
}

// ===== fp32x2 helpers for qk_gemm =====
__device__ __forceinline__ u64 dup2(float x) {
    unsigned u = __float_as_uint(x);
    u64 r;
    asm("mov.b64 %0, {%1, %1};" : "=l"(r) : "r"(u));
    return r;
}
__device__ __forceinline__ void ffma2(u64& acc, u64 a, u64 b) {
    asm("fma.rn.f32x2 %0, %1, %2, %0;" : "+l"(acc) : "l"(a), "l"(b));
}
__device__ __forceinline__ float2 unp2(u64 v) {
    float2 f;
    asm("mov.b64 {%0, %1}, %2;" : "=f"(f.x), "=f"(f.y) : "l"(v));
    return f;
}

// ---------------------------------------------------------------------------
// qk_gemm: Q = h @ Wq^T, K = h @ Wk^T (fp32) + bf16 mirrors in epilogue.
// ---------------------------------------------------------------------------
__device__ __forceinline__ void mm_tile(const float* __restrict__ Ag,
                                        const float* __restrict__ Bg,
                                        u64* As2, float* Bs, u64 acc[8][4]) {
    const int tid = threadIdx.x;
    const int tx = tid & 31, ty = tid >> 5;
    const int arow = tid >> 2;
    const int akg  = (tid & 3) << 3;

    #pragma unroll
    for (int r = 0; r < 8; r++)
        #pragma unroll
        for (int p = 0; p < 4; p++) acc[r][p] = 0ull;

    for (int k0 = 0; k0 < D; k0 += TK) {
        float4 a0 = *(const float4*)(Ag + (size_t)arow * D + k0 + akg);
        float4 a1 = *(const float4*)(Ag + (size_t)arow * D + k0 + akg + 4);
        float4 b[8];
        #pragma unroll
        for (int i = 0; i < 8; i++)
            b[i] = *(const float4*)(Bg + (size_t)tid * D + k0 + i * 4);

        __syncthreads();

        As2[(akg + 0) * AS2_STRIDE + arow] = dup2(a0.x);
        As2[(akg + 1) * AS2_STRIDE + arow] = dup2(a0.y);
        As2[(akg + 2) * AS2_STRIDE + arow] = dup2(a0.z);
        As2[(akg + 3) * AS2_STRIDE + arow] = dup2(a0.w);
        As2[(akg + 4) * AS2_STRIDE + arow] = dup2(a1.x);
        As2[(akg + 5) * AS2_STRIDE + arow] = dup2(a1.y);
        As2[(akg + 6) * AS2_STRIDE + arow] = dup2(a1.z);
        As2[(akg + 7) * AS2_STRIDE + arow] = dup2(a1.w);
        #pragma unroll
        for (int i = 0; i < 8; i++) {
            Bs[(i * 4 + 0) * BS_STRIDE + tid] = b[i].x;
            Bs[(i * 4 + 1) * BS_STRIDE + tid] = b[i].y;
            Bs[(i * 4 + 2) * BS_STRIDE + tid] = b[i].z;
            Bs[(i * 4 + 3) * BS_STRIDE + tid] = b[i].w;
        }
        __syncthreads();

        #pragma unroll 8
        for (int kk = 0; kk < TK; kk++) {
            const u64* ap = As2 + kk * AS2_STRIDE + ty * 8;
            ulonglong2 aa0 = *(const ulonglong2*)(ap + 0);
            ulonglong2 aa1 = *(const ulonglong2*)(ap + 2);
            ulonglong2 aa2 = *(const ulonglong2*)(ap + 4);
            ulonglong2 aa3 = *(const ulonglong2*)(ap + 6);
            const float* bp = Bs + kk * BS_STRIDE;
            ulonglong2 bb0 = *(const ulonglong2*)(bp + tx * 4);
            ulonglong2 bb1 = *(const ulonglong2*)(bp + 128 + tx * 4);
            u64 av[8] = {aa0.x, aa0.y, aa1.x, aa1.y, aa2.x, aa2.y, aa3.x, aa3.y};
            u64 bv[4] = {bb0.x, bb0.y, bb1.x, bb1.y};
            #pragma unroll
            for (int r = 0; r < 8; r++)
                #pragma unroll
                for (int p = 0; p < 4; p++)
                    ffma2(acc[r][p], av[r], bv[p]);
        }
    }
}

__global__ void __launch_bounds__(256, 2)
qk_gemm(const float* __restrict__ h,
        const float* __restrict__ Wq,
        const float* __restrict__ Wk) {
    extern __shared__ char sm[];
    u64* As2 = (u64*)sm;
    float* Bs = (float*)(sm + AS2_BYTES);

    const float* __restrict__ W = blockIdx.z ? Wk : Wq;
    float* __restrict__ out = blockIdx.z ? g_K : g_Q;
    __nv_bfloat16* __restrict__ outb =
        blockIdx.z ? (__nv_bfloat16*)g_Kb4 : (__nv_bfloat16*)g_Qb4;
    const int row0 = blockIdx.y * TM;
    const int col0 = blockIdx.x * TN;

    u64 acc[8][4];
    mm_tile(h + (size_t)row0 * D, W + (size_t)col0 * D, As2, Bs, acc);

    const int tx = threadIdx.x & 31, ty = threadIdx.x >> 5;
    #pragma unroll
    for (int r = 0; r < 8; r++) {
        int row = row0 + ty * 8 + r;
        float2 v0 = unp2(acc[r][0]), v1 = unp2(acc[r][1]);
        size_t off0 = (size_t)row * D + col0 + tx * 4;
        *(float4*)(out + off0) = make_float4(v0.x, v0.y, v1.x, v1.y);
        *(__nv_bfloat162*)(outb + off0)     = __floats2bfloat162_rn(v0.x, v0.y);
        *(__nv_bfloat162*)(outb + off0 + 2) = __floats2bfloat162_rn(v1.x, v1.y);
        float2 v2 = unp2(acc[r][2]), v3 = unp2(acc[r][3]);
        size_t off1 = off0 + 128;
        *(float4*)(out + off1) = make_float4(v2.x, v2.y, v3.x, v3.y);
        *(__nv_bfloat162*)(outb + off1)     = __floats2bfloat162_rn(v2.x, v2.y);
        *(__nv_bfloat162*)(outb + off1 + 2) = __floats2bfloat162_rn(v3.x, v3.y);
    }
}

// ---------------------------------------------------------------------------
// filter_topk: warp-mma bf16 logits (approx) + fused streaming top-28/slab.
// (unchanged from R12 — approx stage only needs candidate-set coverage)
// ---------------------------------------------------------------------------
__global__ void __launch_bounds__(256, 1)
filter_topk(const float* __restrict__ prior, const float* __restrict__ ps_p) {
    extern __shared__ char smem[];
    const uint32_t sb = smem_u32(smem);
    float* Ssh = (float*)(smem + SM_SSH);
    float* cvb = (float*)(smem + SM_CV);
    int*   cib = (int*)(smem + SM_CI);

    const int tid = threadIdx.x;
    const int wid = tid >> 5, l = tid & 31;
    const int wm = wid & 3, wn = wid >> 2;
    const int row0  = blockIdx.y * RPC;
    const int cbase = blockIdx.x * SLAB;
    const float ps = *ps_p;

    const int ra = (l & 7) + ((l >> 3) & 1) * 8;
    const int kadd_a = ((l >> 4) & 1) * 16;
    uint32_t a_base[2]; int amask[2];
    #pragma unroll
    for (int mi = 0; mi < 2; mi++) {
        int row = wm * 32 + mi * 16 + ra;
        a_base[mi] = sb + SM_A + row * 128;
        amask[mi] = (row & 7) << 4;
    }
    const int rb = (l & 7) + ((l >> 4) & 1) * 8;
    const int kadd_b = ((l >> 3) & 1) * 16;
    uint32_t b_base[4]; int bmask[4];
    #pragma unroll
    for (int np = 0; np < 4; np++) {
        int row = wn * 64 + np * 16 + rb;
        b_base[np] = sb + SM_B + row * 128;
        bmask[np] = (row & 7) << 4;
    }

    if (tid < RPC) {
        #pragma unroll
        for (int s = 0; s < CAND; s++) {
            cvb[tid * CAND_STRIDE + s] = NEG_INF;
            cib[tid * CAND_STRIDE + s] = 0;
        }
    }
    float curmin = NEG_INF;
    int minpos = 0;

    const __nv_bfloat16* qb  = (const __nv_bfloat16*)g_Qb4;
    const __nv_bfloat16* kbg = (const __nv_bfloat16*)g_Kb4;

    float4 av[4], bv[4];
    {
        #pragma unroll
        for (int i = 0; i < 4; i++) {
            int u = tid + i * 256, row = u >> 3, c16 = u & 7;
            av[i] = *(const float4*)(qb + (size_t)(row0 + row) * D + c16 * 8);
            bv[i] = *(const float4*)(kbg + (size_t)(cbase + row) * D + c16 * 8);
        }
    }

    int it = 0;
    for (int t = 0; t < FTILES; t++) {
        const int colbase = cbase + t * FTN;
        float acc[2][8][4];
        #pragma unroll
        for (int mi = 0; mi < 2; mi++)
            #pragma unroll
            for (int ni = 0; ni < 8; ni++)
                #pragma unroll
                for (int e = 0; e < 4; e++) acc[mi][ni][e] = 0.f;

        for (int c = 0; c < CHUNKS; c++) {
            __syncthreads();
            #pragma unroll
            for (int i = 0; i < 4; i++) {
                int u = tid + i * 256, row = u >> 3, c16 = u & 7;
                uint32_t off = SMEM_SWIZZLE_128B(row * 128 + c16 * 16);
                *(float4*)(smem + SM_A + off) = av[i];
                *(float4*)(smem + SM_B + off) = bv[i];
            }
            __syncthreads();

            {
                int nit = it + 1;
                if (nit == FTILES * CHUNKS) nit = 0;
                int nt = nit >> 3, nc = nit & 7;
                int ncolb = cbase + nt * FTN;
                #pragma unroll
                for (int i = 0; i < 4; i++) {
                    int u = tid + i * 256, row = u >> 3, c16 = u & 7;
                    av[i] = *(const float4*)(qb + (size_t)(row0 + row) * D +
                                             nc * KC + c16 * 8);
                    bv[i] = *(const float4*)(kbg + (size_t)(ncolb + row) * D +
                                             nc * KC + c16 * 8);
                }
                it = nit;
            }

            #pragma unroll
            for (int ks = 0; ks < 4; ks++) {
                const int kb = ks * 32;
                uint32_t a[2][4];
                ldm4(a[0], a_base[0] + ((kb + kadd_a) ^ amask[0]));
                ldm4(a[1], a_base[1] + ((kb + kadd_a) ^ amask[1]));
                uint32_t bq[4][4];
                #pragma unroll
                for (int np = 0; np < 4; np++)
                    ldm4(bq[np], b_base[np] + ((kb + kadd_b) ^ bmask[np]));
                #pragma unroll
                for (int mi = 0; mi < 2; mi++)
                    #pragma unroll
                    for (int ni = 0; ni < 8; ni++)
                        mma16816(acc[mi][ni], a[mi],
                                 bq[ni >> 1][(ni & 1) * 2],
                                 bq[ni >> 1][(ni & 1) * 2 + 1]);
            }
        }

        __syncthreads();
        #pragma unroll
        for (int mi = 0; mi < 2; mi++) {
            #pragma unroll
            for (int ni = 0; ni < 8; ni++) {
                const int lr = wm * 32 + mi * 16 + (l >> 2);
                const int lc = wn * 64 + ni * 8 + (l & 3) * 2;
                const int gi0 = row0 + lr, gi1 = gi0 + 8;
                const int gc = colbase + lc;
                float2 p0 = *(const float2*)(prior + (size_t)gi0 * N + gc);
                float2 p1 = *(const float2*)(prior + (size_t)gi1 * N + gc);
                float v00 = fmaf(ps, p0.x, acc[mi][ni][0] * SCALE);
                float v01 = fmaf(ps, p0.y, acc[mi][ni][1] * SCALE);
                float v10 = fmaf(ps, p1.x, acc[mi][ni][2] * SCALE);
                float v11 = fmaf(ps, p1.y, acc[mi][ni][3] * SCALE);
                if (gc == gi0)     v00 = NEG_INF;
                if (gc + 1 == gi0) v01 = NEG_INF;
                if (gc == gi1)     v10 = NEG_INF;
                if (gc + 1 == gi1) v11 = NEG_INF;
                *(float2*)(Ssh + lr * SSH_STRIDE + lc) = make_float2(v00, v01);
                *(float2*)(Ssh + (lr + 8) * SSH_STRIDE + lc) = make_float2(v10, v11);
            }
        }
        __syncthreads();

        if (tid < RPC) {
            const float* srow = Ssh + tid * SSH_STRIDE;
            float* cvr = cvb + tid * CAND_STRIDE;
            int*   cir = cib + tid * CAND_STRIDE;
            for (int j = 0; j < FTN; j++) {
                float v = srow[j];
                if (v > curmin) {
                    cvr[minpos] = v;
                    cir[minpos] = colbase + j;
                    float m = cvr[0]; int mp = 0;
                    #pragma unroll
                    for (int s = 1; s < CAND; s++) {
                        float tv = cvr[s];
                        if (tv < m) { m = tv; mp = s; }
                    }
                    curmin = m; minpos = mp;
                }
            }
        }
    }

    __syncthreads();
    if (tid < RPC) {
        const int row = row0 + tid;
        size_t base = ((size_t)row * CSPLIT + blockIdx.x) * CAND;
        #pragma unroll
        for (int s = 0; s < CAND; s++) {
            g_cand_v[base + s] = cvb[tid * CAND_STRIDE + s];
            g_cand_i[base + s] = cib[tid * CAND_STRIDE + s];
        }
    }
}

// ---------------------------------------------------------------------------
// Zero the 256 MB output.
// ---------------------------------------------------------------------------
__global__ void zero_out(float4* __restrict__ out) {
    size_t i = (size_t)blockIdx.x * blockDim.x + threadIdx.x;
    const size_t stride = (size_t)gridDim.x * blockDim.x;
    const size_t n = (size_t)N * N / 4;
    const float4 z = make_float4(0.f, 0.f, 0.f, 0.f);
    for (; i < n; i += stride) out[i] = z;
}

// ---------------------------------------------------------------------------
// rescue: merge 112 approx candidates -> approx top-32 -> EXACT fp32
// recompute (bit-identical to the R4 reference-passing arithmetic: single
// fp32 accumulator, plain ascending-k fma chain over g_Q/g_K, then
// fmaf(ps, prior, acc*SCALE)) -> exact top-20 (tie-break: lower col) ->
// softmax -> scatter. One warp per row; lane = candidate.
// ---------------------------------------------------------------------------
#define ROWS_PER_BLK 8
__global__ void __launch_bounds__(256, 4)
rescue(const float* __restrict__ prior, const float* __restrict__ ps_p,
       float* __restrict__ out) {
    const int w = threadIdx.x >> 5, lane = threadIdx.x & 31;
    const int row = blockIdx.x * ROWS_PER_BLK + w;

    __shared__ float4 qs4[ROWS_PER_BLK][D / 4];
    __shared__ float  cv[ROWS_PER_BLK][CSPLIT * CAND];
    __shared__ int    ci[ROWS_PER_BLK][CSPLIT * CAND];
    __shared__ float  sv[ROWS_PER_BLK][C_RES];
    __shared__ int    scol[ROWS_PER_BLK][C_RES];
    __shared__ float  evs[ROWS_PER_BLK][C_RES];

    // load q row + candidates (per warp)
    const float4* qg = (const float4*)(g_Q + (size_t)row * D);
    #pragma unroll
    for (int i = 0; i < D / 4 / 32; i++)
        qs4[w][lane + i * 32] = qg[lane + i * 32];
    for (int j = lane; j < CSPLIT * CAND; j += 32) {
        size_t b = (size_t)row * CSPLIT * CAND + j;
        cv[w][j] = g_cand_v[b];
        ci[w][j] = g_cand_i[b];
    }
    __syncwarp();

    // approx merge: top-32 of 112 by approx value (lane 0, serial)
    if (lane == 0) {
        #pragma unroll
        for (int s = 0; s < C_RES; s++) { sv[w][s] = NEG_INF; scol[w][s] = 0; }
        float cm = NEG_INF; int mp = 0;
        for (int j = 0; j < CSPLIT * CAND; j++) {
            float v = cv[w][j];
            if (v > cm) {
                sv[w][mp] = v; scol[w][mp] = ci[w][j];
                float m = sv[w][0]; int q = 0;
                #pragma unroll
                for (int s = 1; s < C_RES; s++)
                    if (sv[w][s] < m) { m = sv[w][s]; q = s; }
                cm = m; mp = q;
            }
        }
    }
    __syncwarp();

    const float ps = *ps_p;

    // exact recompute, one candidate per lane. BIT-IDENTICAL to the R4
    // logits: acc starts at 0, fma over k = 0..511 strictly ascending.
    {
        const int col = scol[w][lane];
        const float4* kr = (const float4*)(g_K + (size_t)col * D);
        float acc = 0.f;
        #pragma unroll 4
        for (int i = 0; i < D / 4; i++) {
            float4 qv = qs4[w][i];
            float4 kv = kr[i];
            acc = fmaf(qv.x, kv.x, acc);
            acc = fmaf(qv.y, kv.y, acc);
            acc = fmaf(qv.z, kv.z, acc);
            acc = fmaf(qv.w, kv.w, acc);
        }
        evs[w][lane] = fmaf(ps, prior[(size_t)row * N + col], acc * SCALE);
    }
    __syncwarp();

    // exact top-20 (ties -> lower column, matching jax.lax.top_k), softmax,
    // scatter. Serial on lane 0.
    if (lane == 0) {
        unsigned used = 0;
        float selv[TOPK]; int selc[TOPK];
        #pragma unroll
        for (int t = 0; t < TOPK; t++) {
            float best = NEG_INF; int bcol = 0x7fffffff; int bj = 0;
            #pragma unroll
            for (int j = 0; j < C_RES; j++) {
                if ((used >> j) & 1u) continue;
                float v = evs[w][j];
                int c = scol[w][j];
                if (v > best || (v == best && c < bcol)) {
                    best = v; bcol = c; bj = j;
                }
            }
            used |= 1u << bj;
            selv[t] = best;
            selc[t] = bcol;
        }
        const float mx = selv[0];
        float e[TOPK]; float sum = 0.f;
        #pragma unroll
        for (int t = 0; t < TOPK; t++) { e[t] = expf(selv[t] - mx); sum += e[t]; }
        const float inv = 1.0f / sum;
        size_t rbase = (size_t)row * N;
        #pragma unroll
        for (int t = 0; t < TOPK; t++)
            out[rbase + selc[t]] = e[t] * inv;
    }
}

// ---------------------------------------------------------------------------
extern "C" void kernel_launch(void* const* d_in, const int* in_sizes, int n_in,
                              void* d_out, int out_size) {
    const float* h      = (const float*)d_in[0];
    const float* prior  = (const float*)d_in[1];
    const float* Wq     = (const float*)d_in[2];
    const float* Wk     = (const float*)d_in[3];
    const float* pscale = (const float*)d_in[4];
    float* out = (float*)d_out;

    const int qk_smem = AS2_BYTES + BS_BYTES;
    cudaFuncSetAttribute(qk_gemm, cudaFuncAttributeMaxDynamicSharedMemorySize,
                         qk_smem);
    cudaFuncSetAttribute(filter_topk,
                         cudaFuncAttributeMaxDynamicSharedMemorySize, SM_TOTAL);

    zero_out<<<8192, 256>>>((float4*)out);

    qk_gemm<<<dim3(D / TN, N / TM, 2), 256, qk_smem>>>(h, Wq, Wk);

    filter_topk<<<dim3(CSPLIT, N / RPC), 256, SM_TOTAL>>>(prior, pscale);

    rescue<<<N / ROWS_PER_BLK, 256>>>(prior, pscale, out);
}

// round 14
// speedup vs baseline: 2.0661x; 1.1418x over previous
#include <cuda_runtime.h>
#include <cuda_bf16.h>
#include <math.h>
#include <stdint.h>

#define N 8192
#define D 512
#define TOPK 20
#define SCALE 0.04419417382415922f   // 1/sqrt(512)
#define NEG_INF (__int_as_float(0xff800000))

typedef unsigned long long u64;

// ===== qk_gemm (fp32, FFMA2) config =====
#define TM 64
#define TN 256
#define TK 32
#define AS2_STRIDE (TM + 2)
#define BS_STRIDE  (TN + 4)
#define AS2_BYTES (TK * AS2_STRIDE * 8)
#define BS_BYTES  (TK * BS_STRIDE * 4)

// ===== filter config =====
#define RPC 128
#define CSPLIT 4
#define SLAB (N / CSPLIT)            // 2048
#define FTN 128
#define FTILES (SLAB / FTN)          // 16
#define KC 64
#define CHUNKS (D / KC)              // 8
#define TOTAL_CHUNKS (FTILES * CHUNKS)
#define CAND 28
#define CAND_STRIDE 29
#define NCAND (CSPLIT * CAND)        // 112
#define C_RES 32

// filter smem layout (bytes): A bufs [0,32K), B bufs [32K,64K), Ssh, lists
#define SM_BBASE 32768
#define SM_SSH 65536
#define SSH_STRIDE 132
#define SM_CV (SM_SSH + RPC * SSH_STRIDE * 4)     // 133120
#define SM_CI (SM_CV + RPC * CAND_STRIDE * 4)     // 147968
#define SM_TOTAL (SM_CI + RPC * CAND_STRIDE * 4)  // 162816

#define SMEM_SWIZZLE_128B(o) ((o) ^ (((o) >> 3) & 0x70))

// ===== device scratch =====
__device__ float g_Q[N * D];
__device__ float g_K[N * D];
__device__ float4 g_Qb4[N * D / 8];
__device__ float4 g_Kb4[N * D / 8];
__device__ float g_cand_v[N * NCAND];
__device__ int   g_cand_i[N * NCAND];

// ===== PTX helpers (sm_80-era; safe at target sm_103) =====
__device__ __forceinline__ uint32_t smem_u32(const void* p) {
    uint32_t a;
    asm("{ .reg .u64 t; cvta.to.shared.u64 t, %1; cvt.u32.u64 %0, t; }"
        : "=r"(a) : "l"(p));
    return a;
}
__device__ __forceinline__ void ldm4(uint32_t* r, uint32_t addr) {
    asm volatile("ldmatrix.sync.aligned.m8n8.x4.shared.b16 {%0,%1,%2,%3}, [%4];"
        : "=r"(r[0]), "=r"(r[1]), "=r"(r[2]), "=r"(r[3]) : "r"(addr));
}
__device__ __forceinline__ void mma16816(float* c, const uint32_t* a,
                                         uint32_t b0, uint32_t b1) {
    asm volatile(
        "mma.sync.aligned.m16n8k16.row.col.f32.bf16.bf16.f32 "
        "{%0,%1,%2,%3}, {%4,%5,%6,%7}, {%8,%9}, {%0,%1,%2,%3};"
        : "+f"(c[0]), "+f"(c[1]), "+f"(c[2]), "+f"(c[3])
        : "r"(a[0]), "r"(a[1]), "r"(a[2]), "r"(a[3]), "r"(b0), "r"(b1));
}
__device__ __forceinline__ void cp_async16(uint32_t saddr, const void* g) {
    asm volatile("cp.async.cg.shared.global [%0], [%1], 16;"
                 :: "r"(saddr), "l"(g));
}
#define CP_COMMIT() asm volatile("cp.async.commit_group;")
#define CP_WAIT(n)  asm volatile("cp.async.wait_group %0;" :: "n"(n))

// ===== fp32x2 helpers for qk_gemm =====
__device__ __forceinline__ u64 dup2(float x) {
    unsigned u = __float_as_uint(x);
    u64 r;
    asm("mov.b64 %0, {%1, %1};" : "=l"(r) : "r"(u));
    return r;
}
__device__ __forceinline__ void ffma2(u64& acc, u64 a, u64 b) {
    asm("fma.rn.f32x2 %0, %1, %2, %0;" : "+l"(acc) : "l"(a), "l"(b));
}
__device__ __forceinline__ float2 unp2(u64 v) {
    float2 f;
    asm("mov.b64 {%0, %1}, %2;" : "=f"(f.x), "=f"(f.y) : "l"(v));
    return f;
}

// ---------------------------------------------------------------------------
// qk_gemm: Q = h @ Wq^T, K = h @ Wk^T (fp32) + bf16 mirrors (unchanged).
// ---------------------------------------------------------------------------
__device__ __forceinline__ void mm_tile(const float* __restrict__ Ag,
                                        const float* __restrict__ Bg,
                                        u64* As2, float* Bs, u64 acc[8][4]) {
    const int tid = threadIdx.x;
    const int tx = tid & 31, ty = tid >> 5;
    const int arow = tid >> 2;
    const int akg  = (tid & 3) << 3;

    #pragma unroll
    for (int r = 0; r < 8; r++)
        #pragma unroll
        for (int p = 0; p < 4; p++) acc[r][p] = 0ull;

    for (int k0 = 0; k0 < D; k0 += TK) {
        float4 a0 = *(const float4*)(Ag + (size_t)arow * D + k0 + akg);
        float4 a1 = *(const float4*)(Ag + (size_t)arow * D + k0 + akg + 4);
        float4 b[8];
        #pragma unroll
        for (int i = 0; i < 8; i++)
            b[i] = *(const float4*)(Bg + (size_t)tid * D + k0 + i * 4);

        __syncthreads();

        As2[(akg + 0) * AS2_STRIDE + arow] = dup2(a0.x);
        As2[(akg + 1) * AS2_STRIDE + arow] = dup2(a0.y);
        As2[(akg + 2) * AS2_STRIDE + arow] = dup2(a0.z);
        As2[(akg + 3) * AS2_STRIDE + arow] = dup2(a0.w);
        As2[(akg + 4) * AS2_STRIDE + arow] = dup2(a1.x);
        As2[(akg + 5) * AS2_STRIDE + arow] = dup2(a1.y);
        As2[(akg + 6) * AS2_STRIDE + arow] = dup2(a1.z);
        As2[(akg + 7) * AS2_STRIDE + arow] = dup2(a1.w);
        #pragma unroll
        for (int i = 0; i < 8; i++) {
            Bs[(i * 4 + 0) * BS_STRIDE + tid] = b[i].x;
            Bs[(i * 4 + 1) * BS_STRIDE + tid] = b[i].y;
            Bs[(i * 4 + 2) * BS_STRIDE + tid] = b[i].z;
            Bs[(i * 4 + 3) * BS_STRIDE + tid] = b[i].w;
        }
        __syncthreads();

        #pragma unroll 8
        for (int kk = 0; kk < TK; kk++) {
            const u64* ap = As2 + kk * AS2_STRIDE + ty * 8;
            ulonglong2 aa0 = *(const ulonglong2*)(ap + 0);
            ulonglong2 aa1 = *(const ulonglong2*)(ap + 2);
            ulonglong2 aa2 = *(const ulonglong2*)(ap + 4);
            ulonglong2 aa3 = *(const ulonglong2*)(ap + 6);
            const float* bp = Bs + kk * BS_STRIDE;
            ulonglong2 bb0 = *(const ulonglong2*)(bp + tx * 4);
            ulonglong2 bb1 = *(const ulonglong2*)(bp + 128 + tx * 4);
            u64 av[8] = {aa0.x, aa0.y, aa1.x, aa1.y, aa2.x, aa2.y, aa3.x, aa3.y};
            u64 bv[4] = {bb0.x, bb0.y, bb1.x, bb1.y};
            #pragma unroll
            for (int r = 0; r < 8; r++)
                #pragma unroll
                for (int p = 0; p < 4; p++)
                    ffma2(acc[r][p], av[r], bv[p]);
        }
    }
}

__global__ void __launch_bounds__(256, 2)
qk_gemm(const float* __restrict__ h,
        const float* __restrict__ Wq,
        const float* __restrict__ Wk) {
    extern __shared__ char sm[];
    u64* As2 = (u64*)sm;
    float* Bs = (float*)(sm + AS2_BYTES);

    const float* __restrict__ W = blockIdx.z ? Wk : Wq;
    float* __restrict__ out = blockIdx.z ? g_K : g_Q;
    __nv_bfloat16* __restrict__ outb =
        blockIdx.z ? (__nv_bfloat16*)g_Kb4 : (__nv_bfloat16*)g_Qb4;
    const int row0 = blockIdx.y * TM;
    const int col0 = blockIdx.x * TN;

    u64 acc[8][4];
    mm_tile(h + (size_t)row0 * D, W + (size_t)col0 * D, As2, Bs, acc);

    const int tx = threadIdx.x & 31, ty = threadIdx.x >> 5;
    #pragma unroll
    for (int r = 0; r < 8; r++) {
        int row = row0 + ty * 8 + r;
        float2 v0 = unp2(acc[r][0]), v1 = unp2(acc[r][1]);
        size_t off0 = (size_t)row * D + col0 + tx * 4;
        *(float4*)(out + off0) = make_float4(v0.x, v0.y, v1.x, v1.y);
        *(__nv_bfloat162*)(outb + off0)     = __floats2bfloat162_rn(v0.x, v0.y);
        *(__nv_bfloat162*)(outb + off0 + 2) = __floats2bfloat162_rn(v1.x, v1.y);
        float2 v2 = unp2(acc[r][2]), v3 = unp2(acc[r][3]);
        size_t off1 = off0 + 128;
        *(float4*)(out + off1) = make_float4(v2.x, v2.y, v3.x, v3.y);
        *(__nv_bfloat162*)(outb + off1)     = __floats2bfloat162_rn(v2.x, v2.y);
        *(__nv_bfloat162*)(outb + off1 + 2) = __floats2bfloat162_rn(v3.x, v3.y);
    }
}

// ---------------------------------------------------------------------------
// filter_topk: warp-mma bf16 approx logits + streaming top-28/slab.
// cp.async double-buffered A/B; group-max fast scan.
// ---------------------------------------------------------------------------
__device__ __forceinline__ void filter_issue_chunk(
    const __nv_bfloat16* qb, const __nv_bfloat16* kbg,
    uint32_t sb, int tid, int row0, int cbase, int it) {
    const int t = it >> 3, c = it & 7;
    const __nv_bfloat16* asrc = qb + (size_t)row0 * D + c * KC;
    const __nv_bfloat16* bsrc = kbg + (size_t)(cbase + t * FTN) * D + c * KC;
    const uint32_t bufoff = (uint32_t)(it & 1) * 16384u;
    #pragma unroll
    for (int i = 0; i < 4; i++) {
        int u = tid + i * 256, row = u >> 3, c16 = u & 7;
        uint32_t off = SMEM_SWIZZLE_128B((uint32_t)(row * 128 + c16 * 16));
        cp_async16(sb + bufoff + off, asrc + (size_t)row * D + c16 * 8);
        cp_async16(sb + SM_BBASE + bufoff + off, bsrc + (size_t)row * D + c16 * 8);
    }
    CP_COMMIT();
}

__global__ void __launch_bounds__(256, 1)
filter_topk(const float* __restrict__ prior, const float* __restrict__ ps_p) {
    extern __shared__ char smem[];
    const uint32_t sb = smem_u32(smem);
    float* Ssh = (float*)(smem + SM_SSH);
    float* cvb = (float*)(smem + SM_CV);
    int*   cib = (int*)(smem + SM_CI);

    const int tid = threadIdx.x;
    const int wid = tid >> 5, l = tid & 31;
    const int wm = wid & 3, wn = wid >> 2;
    const int row0  = blockIdx.y * RPC;
    const int cbase = blockIdx.x * SLAB;
    const float ps = *ps_p;

    // ldmatrix lane addressing (buf-0 relative; add bufoff at use)
    const int ra = (l & 7) + ((l >> 3) & 1) * 8;
    const int kadd_a = ((l >> 4) & 1) * 16;
    uint32_t a_base[2]; int amask[2];
    #pragma unroll
    for (int mi = 0; mi < 2; mi++) {
        int row = wm * 32 + mi * 16 + ra;
        a_base[mi] = sb + row * 128;
        amask[mi] = (row & 7) << 4;
    }
    const int rb = (l & 7) + ((l >> 4) & 1) * 8;
    const int kadd_b = ((l >> 3) & 1) * 16;
    uint32_t b_base[4]; int bmask[4];
    #pragma unroll
    for (int np = 0; np < 4; np++) {
        int row = wn * 64 + np * 16 + rb;
        b_base[np] = sb + SM_BBASE + row * 128;
        bmask[np] = (row & 7) << 4;
    }

    if (tid < RPC) {
        #pragma unroll
        for (int s = 0; s < CAND; s++) {
            cvb[tid * CAND_STRIDE + s] = NEG_INF;
            cib[tid * CAND_STRIDE + s] = 0;
        }
    }
    float curmin = NEG_INF;
    int minpos = 0;

    const __nv_bfloat16* qb  = (const __nv_bfloat16*)g_Qb4;
    const __nv_bfloat16* kbg = (const __nv_bfloat16*)g_Kb4;

    // prologue: chunk 0 in flight
    filter_issue_chunk(qb, kbg, sb, tid, row0, cbase, 0);

    for (int t = 0; t < FTILES; t++) {
        const int colbase = cbase + t * FTN;
        float acc[2][8][4];
        #pragma unroll
        for (int mi = 0; mi < 2; mi++)
            #pragma unroll
            for (int ni = 0; ni < 8; ni++)
                #pragma unroll
                for (int e = 0; e < 4; e++) acc[mi][ni][e] = 0.f;

        for (int c = 0; c < CHUNKS; c++) {
            const int it = t * CHUNKS + c;
            const uint32_t bufoff = (uint32_t)(it & 1) * 16384u;
            if (it + 1 < TOTAL_CHUNKS) {
                filter_issue_chunk(qb, kbg, sb, tid, row0, cbase, it + 1);
                CP_WAIT(1);     // chunk `it` landed
            } else {
                CP_WAIT(0);
            }
            __syncthreads();

            #pragma unroll
            for (int ks = 0; ks < 4; ks++) {
                const int kb = ks * 32;
                uint32_t a[2][4];
                ldm4(a[0], a_base[0] + bufoff + ((kb + kadd_a) ^ amask[0]));
                ldm4(a[1], a_base[1] + bufoff + ((kb + kadd_a) ^ amask[1]));
                uint32_t bq[4][4];
                #pragma unroll
                for (int np = 0; np < 4; np++)
                    ldm4(bq[np], b_base[np] + bufoff + ((kb + kadd_b) ^ bmask[np]));
                #pragma unroll
                for (int mi = 0; mi < 2; mi++)
                    #pragma unroll
                    for (int ni = 0; ni < 8; ni++)
                        mma16816(acc[mi][ni], a[mi],
                                 bq[ni >> 1][(ni & 1) * 2],
                                 bq[ni >> 1][(ni & 1) * 2 + 1]);
            }
            __syncthreads();   // all reads of this buf done before it+2 lands
        }

        // epilogue: scale + prior + diag mask -> Ssh
        #pragma unroll
        for (int mi = 0; mi < 2; mi++) {
            #pragma unroll
            for (int ni = 0; ni < 8; ni++) {
                const int lr = wm * 32 + mi * 16 + (l >> 2);
                const int lc = wn * 64 + ni * 8 + (l & 3) * 2;
                const int gi0 = row0 + lr, gi1 = gi0 + 8;
                const int gc = colbase + lc;
                float2 p0 = *(const float2*)(prior + (size_t)gi0 * N + gc);
                float2 p1 = *(const float2*)(prior + (size_t)gi1 * N + gc);
                float v00 = fmaf(ps, p0.x, acc[mi][ni][0] * SCALE);
                float v01 = fmaf(ps, p0.y, acc[mi][ni][1] * SCALE);
                float v10 = fmaf(ps, p1.x, acc[mi][ni][2] * SCALE);
                float v11 = fmaf(ps, p1.y, acc[mi][ni][3] * SCALE);
                if (gc == gi0)     v00 = NEG_INF;
                if (gc + 1 == gi0) v01 = NEG_INF;
                if (gc == gi1)     v10 = NEG_INF;
                if (gc + 1 == gi1) v11 = NEG_INF;
                *(float2*)(Ssh + lr * SSH_STRIDE + lc) = make_float2(v00, v01);
                *(float2*)(Ssh + (lr + 8) * SSH_STRIDE + lc) = make_float2(v10, v11);
            }
        }
        __syncthreads();

        // fast scan: group-max gate, then insert only if a group can beat curmin
        if (tid < RPC) {
            const float* srow = Ssh + tid * SSH_STRIDE;
            float* cvr = cvb + tid * CAND_STRIDE;
            int*   cir = cib + tid * CAND_STRIDE;
            #pragma unroll
            for (int g = 0; g < 4; g++) {
                const float4* gp4 = (const float4*)(srow + g * 32);
                float4 x0 = gp4[0], x1 = gp4[1], x2 = gp4[2], x3 = gp4[3];
                float4 x4 = gp4[4], x5 = gp4[5], x6 = gp4[6], x7 = gp4[7];
                float m01 = fmaxf(fmaxf(fmaxf(x0.x, x0.y), fmaxf(x0.z, x0.w)),
                                  fmaxf(fmaxf(x1.x, x1.y), fmaxf(x1.z, x1.w)));
                float m23 = fmaxf(fmaxf(fmaxf(x2.x, x2.y), fmaxf(x2.z, x2.w)),
                                  fmaxf(fmaxf(x3.x, x3.y), fmaxf(x3.z, x3.w)));
                float m45 = fmaxf(fmaxf(fmaxf(x4.x, x4.y), fmaxf(x4.z, x4.w)),
                                  fmaxf(fmaxf(x5.x, x5.y), fmaxf(x5.z, x5.w)));
                float m67 = fmaxf(fmaxf(fmaxf(x6.x, x6.y), fmaxf(x6.z, x6.w)),
                                  fmaxf(fmaxf(x7.x, x7.y), fmaxf(x7.z, x7.w)));
                float gm = fmaxf(fmaxf(m01, m23), fmaxf(m45, m67));
                if (gm > curmin) {
                    const float* gp = srow + g * 32;
                    const int c0 = colbase + g * 32;
                    for (int j = 0; j < 32; j++) {
                        float v = gp[j];
                        if (v > curmin) {
                            cvr[minpos] = v;
                            cir[minpos] = c0 + j;
                            float m = cvr[0]; int mp = 0;
                            #pragma unroll
                            for (int s = 1; s < CAND; s++) {
                                float tv = cvr[s];
                                if (tv < m) { m = tv; mp = s; }
                            }
                            curmin = m; minpos = mp;
                        }
                    }
                }
            }
        }
        // chunk-loop syncthreads of next tile order scan vs. Ssh reuse
    }

    __syncthreads();
    if (tid < RPC) {
        const int row = row0 + tid;
        size_t base = ((size_t)row * CSPLIT + blockIdx.x) * CAND;
        #pragma unroll
        for (int s = 0; s < CAND; s++) {
            g_cand_v[base + s] = cvb[tid * CAND_STRIDE + s];
            g_cand_i[base + s] = cib[tid * CAND_STRIDE + s];
        }
    }
}

// ---------------------------------------------------------------------------
// Zero the 256 MB output.
// ---------------------------------------------------------------------------
__global__ void zero_out(float4* __restrict__ out) {
    size_t i = (size_t)blockIdx.x * blockDim.x + threadIdx.x;
    const size_t stride = (size_t)gridDim.x * blockDim.x;
    const size_t n = (size_t)N * N / 4;
    const float4 z = make_float4(0.f, 0.f, 0.f, 0.f);
    for (; i < n; i += stride) out[i] = z;
}

// ---------------------------------------------------------------------------
// rescue (PARALLEL): rank-count top-32 of 112 approx -> exact fp32 recompute
// (bit-identical ascending-k chain) -> shfl rank top-20 -> softmax -> scatter.
// One warp per row.
// ---------------------------------------------------------------------------
#define ROWS_PER_BLK 8
__global__ void __launch_bounds__(256, 4)
rescue(const float* __restrict__ prior, const float* __restrict__ ps_p,
       float* __restrict__ out) {
    const int w = threadIdx.x >> 5, lane = threadIdx.x & 31;
    const int row = blockIdx.x * ROWS_PER_BLK + w;

    __shared__ float4 qs4[ROWS_PER_BLK][D / 4];
    __shared__ float  cv[ROWS_PER_BLK][NCAND];
    __shared__ int    ci[ROWS_PER_BLK][NCAND];
    __shared__ int    scol_s[ROWS_PER_BLK][C_RES];

    const float4* qg = (const float4*)(g_Q + (size_t)row * D);
    #pragma unroll
    for (int i = 0; i < D / 4 / 32; i++)
        qs4[w][lane + i * 32] = qg[lane + i * 32];
    for (int j = lane; j < NCAND; j += 32) {
        size_t b = (size_t)row * NCAND + j;
        cv[w][j] = g_cand_v[b];
        ci[w][j] = g_cand_i[b];
    }
    __syncwarp();

    // rank-by-counting selection of top-32 under (value desc, index asc)
    float vj[4];
    int cnt4[4] = {0, 0, 0, 0};
    #pragma unroll
    for (int r = 0; r < 4; r++) {
        int j = r * 32 + lane;
        vj[r] = (j < NCAND) ? cv[w][j] : NEG_INF;
    }
    for (int i = 0; i < NCAND; i++) {
        float vi = cv[w][i];
        #pragma unroll
        for (int r = 0; r < 4; r++)
            cnt4[r] += (vi > vj[r]) || (vi == vj[r] && i < r * 32 + lane);
    }
    int base = 0;
    #pragma unroll
    for (int r = 0; r < 4; r++) {
        int j = r * 32 + lane;
        bool sel = (j < NCAND) && (cnt4[r] < C_RES);
        unsigned m = __ballot_sync(0xffffffff, sel);
        if (sel) {
            int pos = base + __popc(m & ((1u << lane) - 1));
            scol_s[w][pos] = ci[w][j];
        }
        base += __popc(m);
    }
    __syncwarp();

    const float ps = *ps_p;
    const int col = scol_s[w][lane];

    // exact recompute — BIT-IDENTICAL to R4/R13 logits: single fp32 acc,
    // strictly ascending k, then fmaf(ps, prior, acc*SCALE).
    float acc = 0.f;
    {
        const float4* kr = (const float4*)(g_K + (size_t)col * D);
        #pragma unroll 4
        for (int i = 0; i < D / 4; i++) {
            float4 qv = qs4[w][i];
            float4 kv = kr[i];
            acc = fmaf(qv.x, kv.x, acc);
            acc = fmaf(qv.y, kv.y, acc);
            acc = fmaf(qv.z, kv.z, acc);
            acc = fmaf(qv.w, kv.w, acc);
        }
    }
    const float ev = fmaf(ps, prior[(size_t)row * N + col], acc * SCALE);

    // exact rank among 32 via shfl: (value desc, col asc) = jax.lax.top_k order
    int rk = 0;
    #pragma unroll
    for (int i = 0; i < C_RES; i++) {
        float vi = __shfl_sync(0xffffffff, ev, i);
        int cli = __shfl_sync(0xffffffff, col, i);
        rk += (vi > ev) || (vi == ev && cli < col);
    }
    const bool sel20 = rk < TOPK;

    float mx = ev;
    #pragma unroll
    for (int o = 16; o; o >>= 1)
        mx = fmaxf(mx, __shfl_xor_sync(0xffffffff, mx, o));
    float e = sel20 ? expf(ev - mx) : 0.f;
    float sum = e;
    #pragma unroll
    for (int o = 16; o; o >>= 1)
        sum += __shfl_xor_sync(0xffffffff, sum, o);
    if (sel20)
        out[(size_t)row * N + col] = e * (1.0f / sum);
}

// ---------------------------------------------------------------------------
extern "C" void kernel_launch(void* const* d_in, const int* in_sizes, int n_in,
                              void* d_out, int out_size) {
    const float* h      = (const float*)d_in[0];
    const float* prior  = (const float*)d_in[1];
    const float* Wq     = (const float*)d_in[2];
    const float* Wk     = (const float*)d_in[3];
    const float* pscale = (const float*)d_in[4];
    float* out = (float*)d_out;

    const int qk_smem = AS2_BYTES + BS_BYTES;
    cudaFuncSetAttribute(qk_gemm, cudaFuncAttributeMaxDynamicSharedMemorySize,
                         qk_smem);
    cudaFuncSetAttribute(filter_topk,
                         cudaFuncAttributeMaxDynamicSharedMemorySize, SM_TOTAL);

    zero_out<<<8192, 256>>>((float4*)out);

    qk_gemm<<<dim3(D / TN, N / TM, 2), 256, qk_smem>>>(h, Wq, Wk);

    filter_topk<<<dim3(CSPLIT, N / RPC), 256, SM_TOTAL>>>(prior, pscale);

    rescue<<<N / ROWS_PER_BLK, 256>>>(prior, pscale, out);
}

// round 17
// speedup vs baseline: 2.4597x; 1.1905x over previous
#include <cuda_runtime.h>
#include <cuda_bf16.h>
#include <math.h>
#include <stdint.h>

#define N 8192
#define D 512
#define TOPK 20
#define SCALE 0.04419417382415922f   // 1/sqrt(512)
#define NEG_INF (__int_as_float(0xff800000))

typedef unsigned long long u64;

// ===== qk_gemm (fp32, FFMA2) config =====
#define TM 64
#define TN 256
#define TK 32
#define AS2_STRIDE (TM + 2)
#define BS_STRIDE  (TN + 4)
#define AS2_BYTES (TK * AS2_STRIDE * 8)
#define BS_BYTES  (TK * BS_STRIDE * 4)

// ===== filter config =====
#define RPC 128
#define CSPLIT 4
#define SLAB (N / CSPLIT)            // 2048
#define FTN 64                       // col tile (reduced for 2 CTAs/SM)
#define FTILES (SLAB / FTN)          // 32
#define KC 64
#define CHUNKS (D / KC)              // 8
#define TOTAL_CHUNKS (FTILES * CHUNKS)  // 256
#define CAND 28
#define CAND_STRIDE 29
#define NCAND (CSPLIT * CAND)        // 112
#define C_RES 32

// filter smem layout (bytes):
//   A bufs: 2 x 16384 @ 0        (128 rows x 128B)
//   B bufs: 2 x  8192 @ 32768    (64 rows x 128B)
//   Ssh   : 128 x 68 x 4 @ 49152
//   lists : cv/ci @ 83968 / 98816 ; total 113664 (-> 2 CTAs/SM)
#define A_BUF_BYTES 16384
#define B_BUF_BYTES 8192
#define SM_BBASE 32768
#define SM_SSH 49152
#define SSH_STRIDE 68
#define SM_CV (SM_SSH + RPC * SSH_STRIDE * 4)     // 83968
#define SM_CI (SM_CV + RPC * CAND_STRIDE * 4)     // 98816
#define SM_TOTAL (SM_CI + RPC * CAND_STRIDE * 4)  // 113664

#define SMEM_SWIZZLE_128B(o) ((o) ^ (((o) >> 3) & 0x70))

// ===== device scratch =====
__device__ float g_Q[N * D];
__device__ float g_K[N * D];
__device__ float4 g_Qb4[N * D / 8];
__device__ float4 g_Kb4[N * D / 8];
__device__ float g_cand_v[N * NCAND];
__device__ int   g_cand_i[N * NCAND];

// ===== PTX helpers (sm_80-era; safe at target sm_103) =====
__device__ __forceinline__ uint32_t smem_u32(const void* p) {
    uint32_t a;
    asm("{ .reg .u64 t; cvta.to.shared.u64 t, %1; cvt.u32.u64 %0, t; }"
        : "=r"(a) : "l"(p));
    return a;
}
__device__ __forceinline__ void ldm4(uint32_t* r, uint32_t addr) {
    asm volatile("ldmatrix.sync.aligned.m8n8.x4.shared.b16 {%0,%1,%2,%3}, [%4];"
        : "=r"(r[0]), "=r"(r[1]), "=r"(r[2]), "=r"(r[3]) : "r"(addr));
}
__device__ __forceinline__ void mma16816(float* c, const uint32_t* a,
                                         uint32_t b0, uint32_t b1) {
    asm volatile(
        "mma.sync.aligned.m16n8k16.row.col.f32.bf16.bf16.f32 "
        "{%0,%1,%2,%3}, {%4,%5,%6,%7}, {%8,%9}, {%0,%1,%2,%3};"
        : "+f"(c[0]), "+f"(c[1]), "+f"(c[2]), "+f"(c[3])
        : "r"(a[0]), "r"(a[1]), "r"(a[2]), "r"(a[3]), "r"(b0), "r"(b1));
}
__device__ __forceinline__ void cp_async16(uint32_t saddr, const void* g) {
    asm volatile("cp.async.cg.shared.global [%0], [%1], 16;"
                 :: "r"(saddr), "l"(g));
}
#define CP_COMMIT() asm volatile("cp.async.commit_group;")
#define CP_WAIT(n)  asm volatile("cp.async.wait_group %0;" :: "n"(n))

// ===== fp32x2 helpers for qk_gemm =====
__device__ __forceinline__ u64 dup2(float x) {
    unsigned u = __float_as_uint(x);
    u64 r;
    asm("mov.b64 %0, {%1, %1};" : "=l"(r) : "r"(u));
    return r;
}
__device__ __forceinline__ void ffma2(u64& acc, u64 a, u64 b) {
    asm("fma.rn.f32x2 %0, %1, %2, %0;" : "+l"(acc) : "l"(a), "l"(b));
}
__device__ __forceinline__ float2 unp2(u64 v) {
    float2 f;
    asm("mov.b64 {%0, %1}, %2;" : "=f"(f.x), "=f"(f.y) : "l"(v));
    return f;
}

// ---------------------------------------------------------------------------
// qk_gemm: Q = h @ Wq^T, K = h @ Wk^T (fp32) + bf16 mirrors (unchanged).
// ---------------------------------------------------------------------------
__device__ __forceinline__ void mm_tile(const float* __restrict__ Ag,
                                        const float* __restrict__ Bg,
                                        u64* As2, float* Bs, u64 acc[8][4]) {
    const int tid = threadIdx.x;
    const int tx = tid & 31, ty = tid >> 5;
    const int arow = tid >> 2;
    const int akg  = (tid & 3) << 3;

    #pragma unroll
    for (int r = 0; r < 8; r++)
        #pragma unroll
        for (int p = 0; p < 4; p++) acc[r][p] = 0ull;

    for (int k0 = 0; k0 < D; k0 += TK) {
        float4 a0 = *(const float4*)(Ag + (size_t)arow * D + k0 + akg);
        float4 a1 = *(const float4*)(Ag + (size_t)arow * D + k0 + akg + 4);
        float4 b[8];
        #pragma unroll
        for (int i = 0; i < 8; i++)
            b[i] = *(const float4*)(Bg + (size_t)tid * D + k0 + i * 4);

        __syncthreads();

        As2[(akg + 0) * AS2_STRIDE + arow] = dup2(a0.x);
        As2[(akg + 1) * AS2_STRIDE + arow] = dup2(a0.y);
        As2[(akg + 2) * AS2_STRIDE + arow] = dup2(a0.z);
        As2[(akg + 3) * AS2_STRIDE + arow] = dup2(a0.w);
        As2[(akg + 4) * AS2_STRIDE + arow] = dup2(a1.x);
        As2[(akg + 5) * AS2_STRIDE + arow] = dup2(a1.y);
        As2[(akg + 6) * AS2_STRIDE + arow] = dup2(a1.z);
        As2[(akg + 7) * AS2_STRIDE + arow] = dup2(a1.w);
        #pragma unroll
        for (int i = 0; i < 8; i++) {
            Bs[(i * 4 + 0) * BS_STRIDE + tid] = b[i].x;
            Bs[(i * 4 + 1) * BS_STRIDE + tid] = b[i].y;
            Bs[(i * 4 + 2) * BS_STRIDE + tid] = b[i].z;
            Bs[(i * 4 + 3) * BS_STRIDE + tid] = b[i].w;
        }
        __syncthreads();

        #pragma unroll 8
        for (int kk = 0; kk < TK; kk++) {
            const u64* ap = As2 + kk * AS2_STRIDE + ty * 8;
            ulonglong2 aa0 = *(const ulonglong2*)(ap + 0);
            ulonglong2 aa1 = *(const ulonglong2*)(ap + 2);
            ulonglong2 aa2 = *(const ulonglong2*)(ap + 4);
            ulonglong2 aa3 = *(const ulonglong2*)(ap + 6);
            const float* bp = Bs + kk * BS_STRIDE;
            ulonglong2 bb0 = *(const ulonglong2*)(bp + tx * 4);
            ulonglong2 bb1 = *(const ulonglong2*)(bp + 128 + tx * 4);
            u64 av[8] = {aa0.x, aa0.y, aa1.x, aa1.y, aa2.x, aa2.y, aa3.x, aa3.y};
            u64 bv[4] = {bb0.x, bb0.y, bb1.x, bb1.y};
            #pragma unroll
            for (int r = 0; r < 8; r++)
                #pragma unroll
                for (int p = 0; p < 4; p++)
                    ffma2(acc[r][p], av[r], bv[p]);
        }
    }
}

__global__ void __launch_bounds__(256, 2)
qk_gemm(const float* __restrict__ h,
        const float* __restrict__ Wq,
        const float* __restrict__ Wk) {
    extern __shared__ char sm[];
    u64* As2 = (u64*)sm;
    float* Bs = (float*)(sm + AS2_BYTES);

    const float* __restrict__ W = blockIdx.z ? Wk : Wq;
    float* __restrict__ out = blockIdx.z ? g_K : g_Q;
    __nv_bfloat16* __restrict__ outb =
        blockIdx.z ? (__nv_bfloat16*)g_Kb4 : (__nv_bfloat16*)g_Qb4;
    const int row0 = blockIdx.y * TM;
    const int col0 = blockIdx.x * TN;

    u64 acc[8][4];
    mm_tile(h + (size_t)row0 * D, W + (size_t)col0 * D, As2, Bs, acc);

    const int tx = threadIdx.x & 31, ty = threadIdx.x >> 5;
    #pragma unroll
    for (int r = 0; r < 8; r++) {
        int row = row0 + ty * 8 + r;
        float2 v0 = unp2(acc[r][0]), v1 = unp2(acc[r][1]);
        size_t off0 = (size_t)row * D + col0 + tx * 4;
        *(float4*)(out + off0) = make_float4(v0.x, v0.y, v1.x, v1.y);
        *(__nv_bfloat162*)(outb + off0)     = __floats2bfloat162_rn(v0.x, v0.y);
        *(__nv_bfloat162*)(outb + off0 + 2) = __floats2bfloat162_rn(v1.x, v1.y);
        float2 v2 = unp2(acc[r][2]), v3 = unp2(acc[r][3]);
        size_t off1 = off0 + 128;
        *(float4*)(out + off1) = make_float4(v2.x, v2.y, v3.x, v3.y);
        *(__nv_bfloat162*)(outb + off1)     = __floats2bfloat162_rn(v2.x, v2.y);
        *(__nv_bfloat162*)(outb + off1 + 2) = __floats2bfloat162_rn(v3.x, v3.y);
    }
}

// ---------------------------------------------------------------------------
// filter_topk: warp-mma bf16 approx logits + streaming top-28/slab.
// 128x64 tile, cp.async double-buffered, 2 CTAs/SM, group-max fast scan.
// 8 warps: wm = wid&3 (32-row groups), wn = wid>>2 (32-col groups).
// ---------------------------------------------------------------------------
__device__ __forceinline__ void filter_issue_chunk(
    const __nv_bfloat16* qb, const __nv_bfloat16* kbg,
    uint32_t sb, int tid, int row0, int cbase, int it) {
    const int t = it >> 3, c = it & 7;
    const __nv_bfloat16* asrc = qb + (size_t)row0 * D + c * KC;
    const __nv_bfloat16* bsrc = kbg + (size_t)(cbase + t * FTN) * D + c * KC;
    const uint32_t boff_a = (uint32_t)(it & 1) * A_BUF_BYTES;
    const uint32_t boff_b = (uint32_t)(it & 1) * B_BUF_BYTES;
    // A: 128 rows x 128B = 1024 x 16B units -> 4 per thread
    #pragma unroll
    for (int i = 0; i < 4; i++) {
        int u = tid + i * 256, row = u >> 3, c16 = u & 7;
        uint32_t off = SMEM_SWIZZLE_128B((uint32_t)(row * 128 + c16 * 16));
        cp_async16(sb + boff_a + off, asrc + (size_t)row * D + c16 * 8);
    }
    // B: 64 rows x 128B = 512 x 16B units -> 2 per thread
    #pragma unroll
    for (int i = 0; i < 2; i++) {
        int u = tid + i * 256, row = u >> 3, c16 = u & 7;
        uint32_t off = SMEM_SWIZZLE_128B((uint32_t)(row * 128 + c16 * 16));
        cp_async16(sb + SM_BBASE + boff_b + off, bsrc + (size_t)row * D + c16 * 8);
    }
    CP_COMMIT();
}

__global__ void __launch_bounds__(256, 2)
filter_topk(const float* __restrict__ prior, const float* __restrict__ ps_p) {
    extern __shared__ char smem[];
    const uint32_t sb = smem_u32(smem);
    float* Ssh = (float*)(smem + SM_SSH);
    float* cvb = (float*)(smem + SM_CV);
    int*   cib = (int*)(smem + SM_CI);

    const int tid = threadIdx.x;
    const int wid = tid >> 5, l = tid & 31;
    const int wm = wid & 3, wn = wid >> 2;
    const int row0  = blockIdx.y * RPC;
    const int cbase = blockIdx.x * SLAB;
    const float ps = *ps_p;

    // ldmatrix lane addressing (buf-0 relative; add buf offset at use)
    const int ra = (l & 7) + ((l >> 3) & 1) * 8;
    const int kadd_a = ((l >> 4) & 1) * 16;
    uint32_t a_base[2]; int amask[2];
    #pragma unroll
    for (int mi = 0; mi < 2; mi++) {
        int row = wm * 32 + mi * 16 + ra;
        a_base[mi] = sb + row * 128;
        amask[mi] = (row & 7) << 4;
    }
    const int rb = (l & 7) + ((l >> 4) & 1) * 8;
    const int kadd_b = ((l >> 3) & 1) * 16;
    uint32_t b_base[2]; int bmask[2];
    #pragma unroll
    for (int np = 0; np < 2; np++) {
        int row = wn * 32 + np * 16 + rb;
        b_base[np] = sb + SM_BBASE + row * 128;
        bmask[np] = (row & 7) << 4;
    }

    if (tid < RPC) {
        #pragma unroll
        for (int s = 0; s < CAND; s++) {
            cvb[tid * CAND_STRIDE + s] = NEG_INF;
            cib[tid * CAND_STRIDE + s] = 0;
        }
    }
    float curmin = NEG_INF;
    int minpos = 0;

    const __nv_bfloat16* qb  = (const __nv_bfloat16*)g_Qb4;
    const __nv_bfloat16* kbg = (const __nv_bfloat16*)g_Kb4;

    filter_issue_chunk(qb, kbg, sb, tid, row0, cbase, 0);

    for (int t = 0; t < FTILES; t++) {
        const int colbase = cbase + t * FTN;
        float acc[2][4][4];
        #pragma unroll
        for (int mi = 0; mi < 2; mi++)
            #pragma unroll
            for (int ni = 0; ni < 4; ni++)
                #pragma unroll
                for (int e = 0; e < 4; e++) acc[mi][ni][e] = 0.f;

        for (int c = 0; c < CHUNKS; c++) {
            const int it = t * CHUNKS + c;
            const uint32_t boff_a = (uint32_t)(it & 1) * A_BUF_BYTES;
            const uint32_t boff_b = (uint32_t)(it & 1) * B_BUF_BYTES;
            if (it + 1 < TOTAL_CHUNKS) {
                filter_issue_chunk(qb, kbg, sb, tid, row0, cbase, it + 1);
                CP_WAIT(1);
            } else {
                CP_WAIT(0);
            }
            __syncthreads();

            #pragma unroll
            for (int ks = 0; ks < 4; ks++) {
                const int kb = ks * 32;
                uint32_t a[2][4];
                ldm4(a[0], a_base[0] + boff_a + ((kb + kadd_a) ^ amask[0]));
                ldm4(a[1], a_base[1] + boff_a + ((kb + kadd_a) ^ amask[1]));
                uint32_t bq[2][4];
                #pragma unroll
                for (int np = 0; np < 2; np++)
                    ldm4(bq[np], b_base[np] + boff_b + ((kb + kadd_b) ^ bmask[np]));
                #pragma unroll
                for (int mi = 0; mi < 2; mi++)
                    #pragma unroll
                    for (int ni = 0; ni < 4; ni++)
                        mma16816(acc[mi][ni], a[mi],
                                 bq[ni >> 1][(ni & 1) * 2],
                                 bq[ni >> 1][(ni & 1) * 2 + 1]);
            }
            __syncthreads();
        }

        // epilogue: scale + prior + diag mask -> Ssh (128 x 64)
        #pragma unroll
        for (int mi = 0; mi < 2; mi++) {
            #pragma unroll
            for (int ni = 0; ni < 4; ni++) {
                const int lr = wm * 32 + mi * 16 + (l >> 2);
                const int lc = wn * 32 + ni * 8 + (l & 3) * 2;
                const int gi0 = row0 + lr, gi1 = gi0 + 8;
                const int gc = colbase + lc;
                float2 p0 = *(const float2*)(prior + (size_t)gi0 * N + gc);
                float2 p1 = *(const float2*)(prior + (size_t)gi1 * N + gc);
                float v00 = fmaf(ps, p0.x, acc[mi][ni][0] * SCALE);
                float v01 = fmaf(ps, p0.y, acc[mi][ni][1] * SCALE);
                float v10 = fmaf(ps, p1.x, acc[mi][ni][2] * SCALE);
                float v11 = fmaf(ps, p1.y, acc[mi][ni][3] * SCALE);
                if (gc == gi0)     v00 = NEG_INF;
                if (gc + 1 == gi0) v01 = NEG_INF;
                if (gc == gi1)     v10 = NEG_INF;
                if (gc + 1 == gi1) v11 = NEG_INF;
                *(float2*)(Ssh + lr * SSH_STRIDE + lc) = make_float2(v00, v01);
                *(float2*)(Ssh + (lr + 8) * SSH_STRIDE + lc) = make_float2(v10, v11);
            }
        }
        __syncthreads();

        // fast scan: group-max gate over 2 groups of 32 cols
        if (tid < RPC) {
            const float* srow = Ssh + tid * SSH_STRIDE;
            float* cvr = cvb + tid * CAND_STRIDE;
            int*   cir = cib + tid * CAND_STRIDE;
            #pragma unroll
            for (int g = 0; g < 2; g++) {
                const float4* gp4 = (const float4*)(srow + g * 32);
                float4 x0 = gp4[0], x1 = gp4[1], x2 = gp4[2], x3 = gp4[3];
                float4 x4 = gp4[4], x5 = gp4[5], x6 = gp4[6], x7 = gp4[7];
                float m01 = fmaxf(fmaxf(fmaxf(x0.x, x0.y), fmaxf(x0.z, x0.w)),
                                  fmaxf(fmaxf(x1.x, x1.y), fmaxf(x1.z, x1.w)));
                float m23 = fmaxf(fmaxf(fmaxf(x2.x, x2.y), fmaxf(x2.z, x2.w)),
                                  fmaxf(fmaxf(x3.x, x3.y), fmaxf(x3.z, x3.w)));
                float m45 = fmaxf(fmaxf(fmaxf(x4.x, x4.y), fmaxf(x4.z, x4.w)),
                                  fmaxf(fmaxf(x5.x, x5.y), fmaxf(x5.z, x5.w)));
                float m67 = fmaxf(fmaxf(fmaxf(x6.x, x6.y), fmaxf(x6.z, x6.w)),
                                  fmaxf(fmaxf(x7.x, x7.y), fmaxf(x7.z, x7.w)));
                float gm = fmaxf(fmaxf(m01, m23), fmaxf(m45, m67));
                if (gm > curmin) {
                    const float* gp = srow + g * 32;
                    const int c0 = colbase + g * 32;
                    for (int j = 0; j < 32; j++) {
                        float v = gp[j];
                        if (v > curmin) {
                            cvr[minpos] = v;
                            cir[minpos] = c0 + j;
                            float m = cvr[0]; int mp = 0;
                            #pragma unroll
                            for (int s = 1; s < CAND; s++) {
                                float tv = cvr[s];
                                if (tv < m) { m = tv; mp = s; }
                            }
                            curmin = m; minpos = mp;
                        }
                    }
                }
            }
        }
        // next tile's chunk-loop __syncthreads orders scan vs. Ssh reuse
    }

    __syncthreads();
    if (tid < RPC) {
        const int row = row0 + tid;
        size_t base = ((size_t)row * CSPLIT + blockIdx.x) * CAND;
        #pragma unroll
        for (int s = 0; s < CAND; s++) {
            g_cand_v[base + s] = cvb[tid * CAND_STRIDE + s];
            g_cand_i[base + s] = cib[tid * CAND_STRIDE + s];
        }
    }
}

// ---------------------------------------------------------------------------
// Zero the 256 MB output.
// ---------------------------------------------------------------------------
__global__ void zero_out(float4* __restrict__ out) {
    size_t i = (size_t)blockIdx.x * blockDim.x + threadIdx.x;
    const size_t stride = (size_t)gridDim.x * blockDim.x;
    const size_t n = (size_t)N * N / 4;
    const float4 z = make_float4(0.f, 0.f, 0.f, 0.f);
    for (; i < n; i += stride) out[i] = z;
}

// ---------------------------------------------------------------------------
// rescue (unchanged from R14): rank-count top-32 -> exact fp32 recompute
// (bit-identical ascending-k chain) -> shfl rank top-20 -> softmax -> scatter.
// ---------------------------------------------------------------------------
#define ROWS_PER_BLK 8
__global__ void __launch_bounds__(256, 4)
rescue(const float* __restrict__ prior, const float* __restrict__ ps_p,
       float* __restrict__ out) {
    const int w = threadIdx.x >> 5, lane = threadIdx.x & 31;
    const int row = blockIdx.x * ROWS_PER_BLK + w;

    __shared__ float4 qs4[ROWS_PER_BLK][D / 4];
    __shared__ float  cv[ROWS_PER_BLK][NCAND];
    __shared__ int    ci[ROWS_PER_BLK][NCAND];
    __shared__ int    scol_s[ROWS_PER_BLK][C_RES];

    const float4* qg = (const float4*)(g_Q + (size_t)row * D);
    #pragma unroll
    for (int i = 0; i < D / 4 / 32; i++)
        qs4[w][lane + i * 32] = qg[lane + i * 32];
    for (int j = lane; j < NCAND; j += 32) {
        size_t b = (size_t)row * NCAND + j;
        cv[w][j] = g_cand_v[b];
        ci[w][j] = g_cand_i[b];
    }
    __syncwarp();

    float vj[4];
    int cnt4[4] = {0, 0, 0, 0};
    #pragma unroll
    for (int r = 0; r < 4; r++) {
        int j = r * 32 + lane;
        vj[r] = (j < NCAND) ? cv[w][j] : NEG_INF;
    }
    for (int i = 0; i < NCAND; i++) {
        float vi = cv[w][i];
        #pragma unroll
        for (int r = 0; r < 4; r++)
            cnt4[r] += (vi > vj[r]) || (vi == vj[r] && i < r * 32 + lane);
    }
    int base = 0;
    #pragma unroll
    for (int r = 0; r < 4; r++) {
        int j = r * 32 + lane;
        bool sel = (j < NCAND) && (cnt4[r] < C_RES);
        unsigned m = __ballot_sync(0xffffffff, sel);
        if (sel) {
            int pos = base + __popc(m & ((1u << lane) - 1));
            scol_s[w][pos] = ci[w][j];
        }
        base += __popc(m);
    }
    __syncwarp();

    const float ps = *ps_p;
    const int col = scol_s[w][lane];

    float acc = 0.f;
    {
        const float4* kr = (const float4*)(g_K + (size_t)col * D);
        #pragma unroll 4
        for (int i = 0; i < D / 4; i++) {
            float4 qv = qs4[w][i];
            float4 kv = kr[i];
            acc = fmaf(qv.x, kv.x, acc);
            acc = fmaf(qv.y, kv.y, acc);
            acc = fmaf(qv.z, kv.z, acc);
            acc = fmaf(qv.w, kv.w, acc);
        }
    }
    const float ev = fmaf(ps, prior[(size_t)row * N + col], acc * SCALE);

    int rk = 0;
    #pragma unroll
    for (int i = 0; i < C_RES; i++) {
        float vi = __shfl_sync(0xffffffff, ev, i);
        int cli = __shfl_sync(0xffffffff, col, i);
        rk += (vi > ev) || (vi == ev && cli < col);
    }
    const bool sel20 = rk < TOPK;

    float mx = ev;
    #pragma unroll
    for (int o = 16; o; o >>= 1)
        mx = fmaxf(mx, __shfl_xor_sync(0xffffffff, mx, o));
    float e = sel20 ? expf(ev - mx) : 0.f;
    float sum = e;
    #pragma unroll
    for (int o = 16; o; o >>= 1)
        sum += __shfl_xor_sync(0xffffffff, sum, o);
    if (sel20)
        out[(size_t)row * N + col] = e * (1.0f / sum);
}

// ---------------------------------------------------------------------------
extern "C" void kernel_launch(void* const* d_in, const int* in_sizes, int n_in,
                              void* d_out, int out_size) {
    const float* h      = (const float*)d_in[0];
    const float* prior  = (const float*)d_in[1];
    const float* Wq     = (const float*)d_in[2];
    const float* Wk     = (const float*)d_in[3];
    const float* pscale = (const float*)d_in[4];
    float* out = (float*)d_out;

    const int qk_smem = AS2_BYTES + BS_BYTES;
    cudaFuncSetAttribute(qk_gemm, cudaFuncAttributeMaxDynamicSharedMemorySize,
                         qk_smem);
    cudaFuncSetAttribute(filter_topk,
                         cudaFuncAttributeMaxDynamicSharedMemorySize, SM_TOTAL);

    zero_out<<<8192, 256>>>((float4*)out);

    qk_gemm<<<dim3(D / TN, N / TM, 2), 256, qk_smem>>>(h, Wq, Wk);

    filter_topk<<<dim3(CSPLIT, N / RPC), 256, SM_TOTAL>>>(prior, pscale);

    rescue<<<N / ROWS_PER_BLK, 256>>>(prior, pscale, out);
}